// round 5
// baseline (speedup 1.0000x reference)
#include <cuda_runtime.h>

#define BATCH 512
#define CIN   12
#define LIN   5000
#define C1    32
#define K1    50
#define S1    10
#define L1    496
#define C2    32
#define K2    25
#define S2    5
#define L2    95
#define LAT   32
#define HID   64
#define TSTEPS L2
#define EPS   1e-5f

// ---------------- device scratch (no allocation allowed) ----------------
// conv1 weights as tap-pairs: [ci][jp(25)][oc(32)] float2 {w[2jp], w[2jp+1]}
__device__ __align__(16) float2 g_w1[CIN * 25 * C1];
// conv2 weights: [ci][t(25)][oc(32)] float
__device__ __align__(16) float g_w2[C2 * 25 * C2];
__device__ float g_y1[BATCH * C1 * L1];
__device__ float g_y2[BATCH * C2 * L2];
__device__ float g_xt[TSTEPS * BATCH * LAT];
__device__ float g_stats1[64];
__device__ float g_stats2[64];
__device__ float g_bn1[64];
__device__ float g_bn2[64];

__device__ __forceinline__ float warp_sum(float v) {
    #pragma unroll
    for (int o = 16; o; o >>= 1) v += __shfl_xor_sync(0xffffffffu, v, o);
    return v;
}

// ---------------- kernel 0: zero stats + build weight layouts ----------
__global__ __launch_bounds__(256) void prep_kernel(
    const float* __restrict__ c1w, const float* __restrict__ c2w)
{
    int gid = blockIdx.x * 256 + threadIdx.x;
    int stride = gridDim.x * 256;
    if (gid < 64) { g_stats1[gid] = 0.f; g_stats2[gid] = 0.f; }
    for (int i = gid; i < CIN * 25 * C1; i += stride) {
        int oc = i & 31;
        int rest = i >> 5;
        int jp = rest % 25;
        int ci = rest / 25;
        const float* ws = c1w + (oc * CIN + ci) * K1 + 2 * jp;
        g_w1[i] = make_float2(ws[0], ws[1]);
    }
    for (int i = gid; i < C2 * 25 * C2; i += stride) {
        int oc = i & 31;
        int rest = i >> 5;
        int t = rest % 25;
        int ci = rest / 25;
        g_w2[i] = c2w[(oc * C2 + ci) * K2 + t];
    }
}

// ---------------- kernel 1: conv1 + BN1 partial stats ----------------
// grid (8, 512); block 256 = 8 warps. warp w: oc0 = (w&3)*8, posgroup = w>>2.
// thread: 8 oc accumulators for ONE position t = tbase + lane + 32*pg.
// Per tap-pair: 1 LDS.64 (conflict-free) + 4 uniform LDG.128 + 16 FFMA.
#define C1_XROW 680

__global__ __launch_bounds__(256, 5) void conv1_kernel(
    const float* __restrict__ x, const float* __restrict__ bias)
{
    __shared__ float x_s[CIN * C1_XROW];   // 32640 B

    const int b     = blockIdx.y;
    const int tbase = blockIdx.x * 64;
    const int tid   = threadIdx.x;

    const int xstart = tbase * S1;
    const int avail  = LIN - xstart;
    for (int i = tid; i < CIN * C1_XROW; i += 256) {
        int ci = i / C1_XROW, p = i % C1_XROW;
        x_s[i] = (p < avail) ? __ldg(x + (size_t)(b * CIN + ci) * LIN + xstart + p) : 0.f;
    }
    __syncthreads();

    const int lane = tid & 31;
    const int w    = tid >> 5;
    const int oc0  = (w & 3) * 8;
    const int pg   = w >> 2;
    const int tl   = lane + 32 * pg;      // local position 0..63
    const int t    = tbase + tl;          // global position
    const bool valid = (t < L1);
    const int p    = tl * S1;             // even -> 8B aligned; max 630+49=679 OK

    float acc[8];
    #pragma unroll
    for (int u = 0; u < 8; u++) acc[u] = 0.f;

    for (int ci = 0; ci < CIN; ci++) {
        const float* xr = x_s + ci * C1_XROW;
        const float2* wr = g_w1 + ci * (25 * C1) + oc0;
        #pragma unroll 5
        for (int jp = 0; jp < 25; jp++) {
            float2 xv = *reinterpret_cast<const float2*>(xr + p + 2 * jp);
            const float4* w4 = reinterpret_cast<const float4*>(wr + jp * C1);
            float4 wa = __ldg(w4 + 0);
            float4 wb = __ldg(w4 + 1);
            float4 wc = __ldg(w4 + 2);
            float4 wd = __ldg(w4 + 3);
            acc[0] += wa.x * xv.x + wa.y * xv.y;
            acc[1] += wa.z * xv.x + wa.w * xv.y;
            acc[2] += wb.x * xv.x + wb.y * xv.y;
            acc[3] += wb.z * xv.x + wb.w * xv.y;
            acc[4] += wc.x * xv.x + wc.y * xv.y;
            acc[5] += wc.z * xv.x + wc.w * xv.y;
            acc[6] += wd.x * xv.x + wd.y * xv.y;
            acc[7] += wd.z * xv.x + wd.w * xv.y;
        }
    }

    #pragma unroll
    for (int u = 0; u < 8; u++) {
        int oc = oc0 + u;
        float v = acc[u] + __ldg(bias + oc);
        if (valid) g_y1[((size_t)b * C1 + oc) * L1 + t] = v;
        float s  = valid ? v : 0.f;
        float s2 = valid ? v * v : 0.f;
        s  = warp_sum(s);
        s2 = warp_sum(s2);
        if (lane == 0) {
            atomicAdd(&g_stats1[oc], s);
            atomicAdd(&g_stats1[32 + oc], s2);
        }
    }
}

// ---------------- kernel 2: BN finalize ----------------
__global__ void bn_finalize_kernel(int which, const float* __restrict__ g,
                                   const float* __restrict__ bsh, float invN)
{
    int c = threadIdx.x;
    if (c < 32) {
        const float* st = which ? g_stats2 : g_stats1;
        float* out = which ? g_bn2 : g_bn1;
        float m = st[c] * invN;
        float v = st[32 + c] * invN - m * m;
        float sc = g[c] * rsqrtf(v + EPS);
        out[c] = sc;
        out[32 + c] = bsh[c] - m * sc;
    }
}

// ---------------- kernel 3: conv2 (BN1+relu at load) + BN2 stats ------
// grid (2, 512): tile 0 covers t in [0,64), tile 1 covers [64,95).
// block 256 = 8 warps; warp w: oc0 = (w&3)*8, pg = w>>2; thread = 8 oc x
// 1 position t_local = lane + 32*pg. x window in smem: 32 x 344 floats.
#define X2ROW 344
#define SMEM2_BYTES (C2 * X2ROW * 4)     // 44032

__global__ __launch_bounds__(256, 5) void conv2_kernel(const float* __restrict__ bias)
{
    extern __shared__ float a_s[];       // [32][344]

    const int tile = blockIdx.x;
    const int b    = blockIdx.y;
    const int tid  = threadIdx.x;

    const int xbase = tile * 320;        // float offset into 496-row
    const int xlen4 = tile ? 44 : 86;    // float4 count per row (176 / 344)

    for (int i = tid; i < C2 * xlen4; i += 256) {
        int ci = i / xlen4, j = i % xlen4;
        float sc = g_bn1[ci], sh = g_bn1[32 + ci];
        float4 v = __ldg(reinterpret_cast<const float4*>(
                       g_y1 + ((size_t)b * C2 + ci) * L1 + xbase) + j);
        v.x = fmaxf(v.x * sc + sh, 0.f);
        v.y = fmaxf(v.y * sc + sh, 0.f);
        v.z = fmaxf(v.z * sc + sh, 0.f);
        v.w = fmaxf(v.w * sc + sh, 0.f);
        reinterpret_cast<float4*>(a_s + ci * X2ROW)[j] = v;
    }
    __syncthreads();

    const int lane = tid & 31;
    const int w    = tid >> 5;
    const int oc0  = (w & 3) * 8;
    const int pg   = w >> 2;
    const int tl   = lane + 32 * pg;
    const int tg   = tile * 64 + tl;

    // whole-warp early out (keeps shfl reductions warp-collective)
    if (tile * 64 + 32 * pg >= L2) return;
    const bool valid = (tg < L2);
    const int p = (valid ? tl : 0) * S2;  // max 315+24=339 < 344

    float acc[8];
    #pragma unroll
    for (int u = 0; u < 8; u++) acc[u] = 0.f;

    for (int ci = 0; ci < C2; ci++) {
        const float* xr = a_s + ci * X2ROW;
        const float* wr = g_w2 + ci * (25 * C2) + oc0;
        #pragma unroll 5
        for (int t = 0; t < 25; t++) {
            float xv = xr[p + t];
            const float4* w4 = reinterpret_cast<const float4*>(wr + t * C2);
            float4 wa = __ldg(w4 + 0);
            float4 wb = __ldg(w4 + 1);
            acc[0] += wa.x * xv;
            acc[1] += wa.y * xv;
            acc[2] += wa.z * xv;
            acc[3] += wa.w * xv;
            acc[4] += wb.x * xv;
            acc[5] += wb.y * xv;
            acc[6] += wb.z * xv;
            acc[7] += wb.w * xv;
        }
    }

    #pragma unroll
    for (int u = 0; u < 8; u++) {
        int oc = oc0 + u;
        float v = acc[u] + __ldg(bias + oc);
        if (valid) g_y2[((size_t)b * C2 + oc) * L2 + tg] = v;
        float s  = valid ? v : 0.f;
        float s2 = valid ? v * v : 0.f;
        s  = warp_sum(s);
        s2 = warp_sum(s2);
        if (lane == 0) {
            atomicAdd(&g_stats2[oc], s);
            atomicAdd(&g_stats2[32 + oc], s2);
        }
    }
}

// ---------------- kernel 4: BN2+relu, input projection, LN1 ----------
__global__ __launch_bounds__(256) void proj_kernel(
    const float* __restrict__ Wi, const float* __restrict__ bi,
    const float* __restrict__ ln1g, const float* __restrict__ ln1b)
{
    __shared__ float a_s[C2 * L2];
    __shared__ float Wi_s[32 * 33];

    const int b = blockIdx.x;
    const int tid = threadIdx.x;
    for (int i = tid; i < C2 * L2; i += 256) {
        int c = i / L2;
        float v = g_y2[(size_t)b * C2 * L2 + i];
        a_s[i] = fmaxf(v * g_bn2[c] + g_bn2[32 + c], 0.f);
    }
    for (int i = tid; i < 32 * 32; i += 256)
        Wi_s[(i >> 5) * 33 + (i & 31)] = Wi[i];
    __syncthreads();

    const int lane = tid & 31;
    const int wp = tid >> 5;
    const float biv = bi[lane];
    const float gv = ln1g[lane], bv = ln1b[lane];

    for (int t = wp; t < L2; t += 8) {
        float z = biv;
        #pragma unroll
        for (int c = 0; c < 32; c++)
            z += Wi_s[lane * 33 + c] * a_s[c * L2 + t];
        float m = warp_sum(z) * (1.f / 32.f);
        float d = z - m;
        float var = warp_sum(d * d) * (1.f / 32.f);
        float r = rsqrtf(var + EPS);
        g_xt[((size_t)t * BATCH + b) * LAT + lane] = d * r * gv + bv;
    }
}

// ---------------- kernel 5: recurrent scan + pool + output proj -------
__global__ __launch_bounds__(128) void rnn_kernel(
    const float* __restrict__ Wh, const float* __restrict__ bh,
    const float* __restrict__ ln2g, const float* __restrict__ ln2b,
    const float* __restrict__ Wr, const float* __restrict__ br,
    const float* __restrict__ Wo, const float* __restrict__ bo,
    float* __restrict__ out)
{
    __shared__ float Wh_s[64 * 33];
    __shared__ float Wr_s[32 * 65];
    __shared__ float Wo_s[32 * 33];

    const int tid = threadIdx.x;
    const int lane = tid & 31;
    const int wp = tid >> 5;
    for (int i = tid; i < 64 * 32; i += 128) Wh_s[(i >> 5) * 33 + (i & 31)] = Wh[i];
    for (int i = tid; i < 32 * 64; i += 128) Wr_s[(i / 64) * 65 + (i % 64)] = Wr[i];
    for (int i = tid; i < 32 * 32; i += 128) Wo_s[(i >> 5) * 33 + (i & 31)] = Wo[i];
    __syncthreads();

    const int b = blockIdx.x * 4 + wp;
    const float bh0 = bh[lane], bh1 = bh[lane + 32];
    const float gA = ln2g[lane], bA = ln2b[lane];
    const float gB = ln2g[lane + 32], bB = ln2b[lane + 32];
    const float brl = br[lane];

    float h = 0.f, psum = 0.f;
    for (int t = 0; t < TSTEPS; t++) {
        float c = g_xt[((size_t)t * BATCH + b) * LAT + lane] + h;
        float a0a = bh0, a0b = 0.f, a1a = bh1, a1b = 0.f;
        #pragma unroll
        for (int j = 0; j < 32; j += 2) {
            float cj0 = __shfl_sync(0xffffffffu, c, j);
            float cj1 = __shfl_sync(0xffffffffu, c, j + 1);
            a0a += Wh_s[lane * 33 + j] * cj0;
            a0b += Wh_s[lane * 33 + j + 1] * cj1;
            a1a += Wh_s[(lane + 32) * 33 + j] * cj0;
            a1b += Wh_s[(lane + 32) * 33 + j + 1] * cj1;
        }
        float a0 = fmaxf(a0a + a0b, 0.f);
        float a1 = fmaxf(a1a + a1b, 0.f);
        float m = warp_sum(a0 + a1) * (1.f / 64.f);
        float d0 = a0 - m, d1 = a1 - m;
        float var = warp_sum(d0 * d0 + d1 * d1) * (1.f / 64.f);
        float r = rsqrtf(var + EPS);
        float n0 = d0 * r * gA + bA;
        float n1 = d1 * r * gB + bB;
        float acca = brl, accb = 0.f;
        #pragma unroll
        for (int i = 0; i < 32; i++) {
            float v0 = __shfl_sync(0xffffffffu, n0, i);
            float v1 = __shfl_sync(0xffffffffu, n1, i);
            acca += Wr_s[lane * 65 + i] * v0;
            accb += Wr_s[lane * 65 + 32 + i] * v1;
        }
        h = tanhf(acca + accb);
        psum += h;
    }
    float p = psum * (1.f / (float)TSTEPS);
    float o = bo[lane];
    #pragma unroll
    for (int j = 0; j < 32; j++)
        o += Wo_s[lane * 33 + j] * __shfl_sync(0xffffffffu, p, j);
    out[b * 32 + lane] = o;
}

// ---------------- launch ----------------
extern "C" void kernel_launch(void* const* d_in, const int* in_sizes, int n_in,
                              void* d_out, int out_size)
{
    const float* x    = (const float*)d_in[0];
    const float* c1w  = (const float*)d_in[1];
    const float* c1b  = (const float*)d_in[2];
    const float* bn1g = (const float*)d_in[3];
    const float* bn1b = (const float*)d_in[4];
    const float* c2w  = (const float*)d_in[5];
    const float* c2b  = (const float*)d_in[6];
    const float* bn2g = (const float*)d_in[7];
    const float* bn2b = (const float*)d_in[8];
    const float* Wi   = (const float*)d_in[9];
    const float* bi   = (const float*)d_in[10];
    const float* ln1g = (const float*)d_in[11];
    const float* ln1b = (const float*)d_in[12];
    const float* Wh   = (const float*)d_in[13];
    const float* bh   = (const float*)d_in[14];
    const float* ln2g = (const float*)d_in[15];
    const float* ln2b = (const float*)d_in[16];
    const float* Wr   = (const float*)d_in[17];
    const float* br   = (const float*)d_in[18];
    const float* Wo   = (const float*)d_in[19];
    const float* bo   = (const float*)d_in[20];
    float* out = (float*)d_out;

    static bool attr_done = false;
    if (!attr_done) {
        cudaFuncSetAttribute(conv2_kernel, cudaFuncAttributeMaxDynamicSharedMemorySize, SMEM2_BYTES);
        attr_done = true;
    }

    prep_kernel<<<64, 256>>>(c1w, c2w);
    conv1_kernel<<<dim3(8, BATCH), 256>>>(x, c1b);
    bn_finalize_kernel<<<1, 32>>>(0, bn1g, bn1b, 1.f / (float)(BATCH * L1));
    conv2_kernel<<<dim3(2, BATCH), 256, SMEM2_BYTES>>>(c2b);
    bn_finalize_kernel<<<1, 32>>>(1, bn2g, bn2b, 1.f / (float)(BATCH * L2));
    proj_kernel<<<BATCH, 256>>>(Wi, bi, ln1g, ln1b);
    rnn_kernel<<<BATCH / 4, 128>>>(Wh, bh, ln2g, ln2b, Wr, br, Wo, bo, out);
}

// round 6
// speedup vs baseline: 1.6923x; 1.6923x over previous
#include <cuda_runtime.h>

#define BATCH 512
#define CIN   12
#define LIN   5000
#define C1    32
#define K1    50
#define S1    10
#define L1    496
#define C2    32
#define K2    25
#define S2    5
#define L2    95
#define LAT   32
#define HID   64
#define TSTEPS L2
#define EPS   1e-5f

// conv1 weights as tap-pairs: [ci][jp(25)][oc(32)] float2 {w[2jp], w[2jp+1]}
// conv2 weights padded per-oc: [oc][ci][28]
#define C2_WPAD 28
#define C2_OCSTR (C2 * C2_WPAD)          // 896 floats per oc

// ---------------- device scratch (no allocation allowed) ----------------
__device__ __align__(16) float2 g_w1[CIN * 25 * C1];
__device__ __align__(16) float g_w2p[C2 * C2_OCSTR];
__device__ float g_y1[BATCH * C1 * L1];
__device__ float g_y2[BATCH * C2 * L2];
__device__ float g_xt[TSTEPS * BATCH * LAT];
__device__ float g_stats1[64];
__device__ float g_stats2[64];
__device__ float g_bn1[64];
__device__ float g_bn2[64];

__device__ __forceinline__ float warp_sum(float v) {
    #pragma unroll
    for (int o = 16; o; o >>= 1) v += __shfl_xor_sync(0xffffffffu, v, o);
    return v;
}

// ---------------- kernel 0: zero stats + build weight layouts ----------
__global__ __launch_bounds__(256) void prep_kernel(
    const float* __restrict__ c1w, const float* __restrict__ c2w)
{
    int gid = blockIdx.x * 256 + threadIdx.x;
    int stride = gridDim.x * 256;
    if (gid < 64) { g_stats1[gid] = 0.f; g_stats2[gid] = 0.f; }
    // conv1: idx = (ci*25 + jp)*32 + oc
    for (int i = gid; i < CIN * 25 * C1; i += stride) {
        int oc = i & 31;
        int rest = i >> 5;
        int jp = rest % 25;
        int ci = rest / 25;
        const float* ws = c1w + (oc * CIN + ci) * K1 + 2 * jp;
        g_w1[i] = make_float2(ws[0], ws[1]);
    }
    // conv2: [oc][ci][28] padded
    for (int i = gid; i < C2 * C2_OCSTR; i += stride) {
        int j = i % C2_WPAD;
        int rest = i / C2_WPAD;          // oc*32 + ci
        g_w2p[i] = (j < K2) ? c2w[rest * K2 + j] : 0.f;
    }
}

// ---------------- kernel 1: conv1 + BN1 partial stats ----------------
// grid (8, 512); block 128 = 4 warps; warp -> 8 oc; lane -> t0 = tbase+lane,
// t1 = t0+32. x via conflict-free LDS.64 (even stride-10 offsets);
// weights via 4 warp-uniform LDG.128 per tap-pair. 16 independent acc chains.
#define C1_XROW 680

__global__ __launch_bounds__(128) void conv1_kernel(
    const float* __restrict__ x, const float* __restrict__ bias)
{
    __shared__ float x_s[CIN * C1_XROW];   // 32640 B

    const int b     = blockIdx.y;
    const int tbase = blockIdx.x * 64;
    const int tid   = threadIdx.x;

    const int xstart = tbase * S1;
    const int avail  = LIN - xstart;
    for (int i = tid; i < CIN * C1_XROW; i += 128) {
        int ci = i / C1_XROW, p = i % C1_XROW;
        x_s[i] = (p < avail) ? __ldg(x + (size_t)(b * CIN + ci) * LIN + xstart + p) : 0.f;
    }
    __syncthreads();

    const int lane = tid & 31;
    const int oc0  = (tid >> 5) * 8;
    const int p0   = lane * S1;          // even -> 8B aligned
    const int p1   = p0 + 320;

    float acc[8][2];
    #pragma unroll
    for (int u = 0; u < 8; u++) { acc[u][0] = 0.f; acc[u][1] = 0.f; }

    for (int ci = 0; ci < CIN; ci++) {
        const float* xr = x_s + ci * C1_XROW;
        const float2* wr = g_w1 + ci * (25 * C1) + oc0;
        #pragma unroll 5
        for (int jp = 0; jp < 25; jp++) {
            float2 xv0 = *reinterpret_cast<const float2*>(xr + p0 + 2 * jp);
            float2 xv1 = *reinterpret_cast<const float2*>(xr + p1 + 2 * jp);
            const float4* w4 = reinterpret_cast<const float4*>(wr + jp * C1);
            float4 wa = __ldg(w4 + 0);
            float4 wb = __ldg(w4 + 1);
            float4 wc = __ldg(w4 + 2);
            float4 wd = __ldg(w4 + 3);
            acc[0][0] += wa.x * xv0.x + wa.y * xv0.y;
            acc[0][1] += wa.x * xv1.x + wa.y * xv1.y;
            acc[1][0] += wa.z * xv0.x + wa.w * xv0.y;
            acc[1][1] += wa.z * xv1.x + wa.w * xv1.y;
            acc[2][0] += wb.x * xv0.x + wb.y * xv0.y;
            acc[2][1] += wb.x * xv1.x + wb.y * xv1.y;
            acc[3][0] += wb.z * xv0.x + wb.w * xv0.y;
            acc[3][1] += wb.z * xv1.x + wb.w * xv1.y;
            acc[4][0] += wc.x * xv0.x + wc.y * xv0.y;
            acc[4][1] += wc.x * xv1.x + wc.y * xv1.y;
            acc[5][0] += wc.z * xv0.x + wc.w * xv0.y;
            acc[5][1] += wc.z * xv1.x + wc.w * xv1.y;
            acc[6][0] += wd.x * xv0.x + wd.y * xv0.y;
            acc[6][1] += wd.x * xv1.x + wd.y * xv1.y;
            acc[7][0] += wd.z * xv0.x + wd.w * xv0.y;
            acc[7][1] += wd.z * xv1.x + wd.w * xv1.y;
        }
    }

    const int t0g = tbase + lane;
    const int t1g = t0g + 32;
    const bool ok1 = (t1g < L1);
    #pragma unroll
    for (int u = 0; u < 8; u++) {
        int oc = oc0 + u;
        float bsv = __ldg(bias + oc);
        float v0 = acc[u][0] + bsv;
        float v1 = acc[u][1] + bsv;
        g_y1[((size_t)b * C1 + oc) * L1 + t0g] = v0;
        if (ok1) g_y1[((size_t)b * C1 + oc) * L1 + t1g] = v1;
        float s  = v0 + (ok1 ? v1 : 0.f);
        float s2 = v0 * v0 + (ok1 ? v1 * v1 : 0.f);
        s  = warp_sum(s);
        s2 = warp_sum(s2);
        if (lane == 0) {
            atomicAdd(&g_stats1[oc], s);
            atomicAdd(&g_stats1[32 + oc], s2);
        }
    }
}

// ---------------- kernel 2: BN finalize ----------------
__global__ void bn_finalize_kernel(int which, const float* __restrict__ g,
                                   const float* __restrict__ bsh, float invN)
{
    int c = threadIdx.x;
    if (c < 32) {
        const float* st = which ? g_stats2 : g_stats1;
        float* out = which ? g_bn2 : g_bn1;
        float m = st[c] * invN;
        float v = st[32 + c] * invN - m * m;
        float sc = g[c] * rsqrtf(v + EPS);
        out[c] = sc;
        out[32 + c] = bsh[c] - m * sc;
    }
}

// ---------------- kernel 3: conv2 (BN1+relu at load) + BN2 stats ------
// R1-measured config: grid 512; block 256 = 8 warps; warp -> 4 oc;
// lane -> t2 = {lane, lane+32, lane+64}; 12 accumulators/thread.
#define SMEM2_FLOATS (C2 * L1)            // 15872
#define SMEM2_BYTES  (SMEM2_FLOATS * 4)   // 63488

__global__ __launch_bounds__(256) void conv2_kernel(const float* __restrict__ bias)
{
    extern __shared__ float a_s[];        // [32][496]

    const int b = blockIdx.x;
    const int tid = threadIdx.x;

    const float4* y1v = reinterpret_cast<const float4*>(g_y1 + (size_t)b * C2 * L1);
    float4* av = reinterpret_cast<float4*>(a_s);
    for (int i = tid; i < C2 * 124; i += 256) {
        int ci = i / 124;
        float sc = g_bn1[ci], sh = g_bn1[32 + ci];
        float4 v = __ldg(y1v + i);
        v.x = fmaxf(v.x * sc + sh, 0.f);
        v.y = fmaxf(v.y * sc + sh, 0.f);
        v.z = fmaxf(v.z * sc + sh, 0.f);
        v.w = fmaxf(v.w * sc + sh, 0.f);
        av[i] = v;
    }
    __syncthreads();

    const int lane = tid & 31;
    const int oc0  = (tid >> 5) * 4;
    const int p0 = lane * S2;
    const int p1 = p0 + 160;
    const bool ok2 = (lane + 64 < L2);
    const int p2 = ok2 ? p0 + 320 : 0;

    float acc[4][3];
    #pragma unroll
    for (int u = 0; u < 4; u++) { acc[u][0] = 0.f; acc[u][1] = 0.f; acc[u][2] = 0.f; }

    for (int ci = 0; ci < C2; ci++) {
        const float* xr = a_s + ci * L1;
        const float* wr = g_w2p + oc0 * C2_OCSTR + ci * C2_WPAD;
        #pragma unroll
        for (int j = 0; j < 24; j += 4) {
            float x00 = xr[p0 + j], x01 = xr[p0 + j + 1], x02 = xr[p0 + j + 2], x03 = xr[p0 + j + 3];
            float x10 = xr[p1 + j], x11 = xr[p1 + j + 1], x12 = xr[p1 + j + 2], x13 = xr[p1 + j + 3];
            float x20 = xr[p2 + j], x21 = xr[p2 + j + 1], x22 = xr[p2 + j + 2], x23 = xr[p2 + j + 3];
            #pragma unroll
            for (int u = 0; u < 4; u++) {
                float4 wv = __ldg(reinterpret_cast<const float4*>(wr + u * C2_OCSTR + j));
                acc[u][0] += wv.x * x00 + wv.y * x01 + wv.z * x02 + wv.w * x03;
                acc[u][1] += wv.x * x10 + wv.y * x11 + wv.z * x12 + wv.w * x13;
                acc[u][2] += wv.x * x20 + wv.y * x21 + wv.z * x22 + wv.w * x23;
            }
        }
        { // tap 24
            float x0 = xr[p0 + 24], x1 = xr[p1 + 24], x2 = xr[p2 + 24];
            #pragma unroll
            for (int u = 0; u < 4; u++) {
                float wv = __ldg(wr + u * C2_OCSTR + 24);
                acc[u][0] += wv * x0;
                acc[u][1] += wv * x1;
                acc[u][2] += wv * x2;
            }
        }
    }

    #pragma unroll
    for (int u = 0; u < 4; u++) {
        int oc = oc0 + u;
        float bsv = __ldg(bias + oc);
        float v0 = acc[u][0] + bsv;
        float v1 = acc[u][1] + bsv;
        float v2 = acc[u][2] + bsv;
        float* yo = g_y2 + ((size_t)b * C2 + oc) * L2;
        yo[lane] = v0;
        yo[lane + 32] = v1;
        if (ok2) yo[lane + 64] = v2;
        float s  = v0 + v1 + (ok2 ? v2 : 0.f);
        float s2 = v0 * v0 + v1 * v1 + (ok2 ? v2 * v2 : 0.f);
        s  = warp_sum(s);
        s2 = warp_sum(s2);
        if (lane == 0) {
            atomicAdd(&g_stats2[oc], s);
            atomicAdd(&g_stats2[32 + oc], s2);
        }
    }
}

// ---------------- kernel 4: BN2+relu, input projection, LN1 ----------
__global__ __launch_bounds__(256) void proj_kernel(
    const float* __restrict__ Wi, const float* __restrict__ bi,
    const float* __restrict__ ln1g, const float* __restrict__ ln1b)
{
    __shared__ float a_s[C2 * L2];
    __shared__ float Wi_s[32 * 33];

    const int b = blockIdx.x;
    const int tid = threadIdx.x;
    for (int i = tid; i < C2 * L2; i += 256) {
        int c = i / L2;
        float v = g_y2[(size_t)b * C2 * L2 + i];
        a_s[i] = fmaxf(v * g_bn2[c] + g_bn2[32 + c], 0.f);
    }
    for (int i = tid; i < 32 * 32; i += 256)
        Wi_s[(i >> 5) * 33 + (i & 31)] = Wi[i];
    __syncthreads();

    const int lane = tid & 31;
    const int wp = tid >> 5;
    const float biv = bi[lane];
    const float gv = ln1g[lane], bv = ln1b[lane];

    for (int t = wp; t < L2; t += 8) {
        float z = biv;
        #pragma unroll
        for (int c = 0; c < 32; c++)
            z += Wi_s[lane * 33 + c] * a_s[c * L2 + t];
        float m = warp_sum(z) * (1.f / 32.f);
        float d = z - m;
        float var = warp_sum(d * d) * (1.f / 32.f);
        float r = rsqrtf(var + EPS);
        g_xt[((size_t)t * BATCH + b) * LAT + lane] = d * r * gv + bv;
    }
}

// ---------------- kernel 5: recurrent scan + pool + output proj -------
__global__ __launch_bounds__(128) void rnn_kernel(
    const float* __restrict__ Wh, const float* __restrict__ bh,
    const float* __restrict__ ln2g, const float* __restrict__ ln2b,
    const float* __restrict__ Wr, const float* __restrict__ br,
    const float* __restrict__ Wo, const float* __restrict__ bo,
    float* __restrict__ out)
{
    __shared__ float Wh_s[64 * 33];
    __shared__ float Wr_s[32 * 65];
    __shared__ float Wo_s[32 * 33];

    const int tid = threadIdx.x;
    const int lane = tid & 31;
    const int wp = tid >> 5;
    for (int i = tid; i < 64 * 32; i += 128) Wh_s[(i >> 5) * 33 + (i & 31)] = Wh[i];
    for (int i = tid; i < 32 * 64; i += 128) Wr_s[(i / 64) * 65 + (i % 64)] = Wr[i];
    for (int i = tid; i < 32 * 32; i += 128) Wo_s[(i >> 5) * 33 + (i & 31)] = Wo[i];
    __syncthreads();

    const int b = blockIdx.x * 4 + wp;
    const float bh0 = bh[lane], bh1 = bh[lane + 32];
    const float gA = ln2g[lane], bA = ln2b[lane];
    const float gB = ln2g[lane + 32], bB = ln2b[lane + 32];
    const float brl = br[lane];

    float h = 0.f, psum = 0.f;
    for (int t = 0; t < TSTEPS; t++) {
        float c = g_xt[((size_t)t * BATCH + b) * LAT + lane] + h;
        float a0a = bh0, a0b = 0.f, a1a = bh1, a1b = 0.f;
        #pragma unroll
        for (int j = 0; j < 32; j += 2) {
            float cj0 = __shfl_sync(0xffffffffu, c, j);
            float cj1 = __shfl_sync(0xffffffffu, c, j + 1);
            a0a += Wh_s[lane * 33 + j] * cj0;
            a0b += Wh_s[lane * 33 + j + 1] * cj1;
            a1a += Wh_s[(lane + 32) * 33 + j] * cj0;
            a1b += Wh_s[(lane + 32) * 33 + j + 1] * cj1;
        }
        float a0 = fmaxf(a0a + a0b, 0.f);
        float a1 = fmaxf(a1a + a1b, 0.f);
        float m = warp_sum(a0 + a1) * (1.f / 64.f);
        float d0 = a0 - m, d1 = a1 - m;
        float var = warp_sum(d0 * d0 + d1 * d1) * (1.f / 64.f);
        float r = rsqrtf(var + EPS);
        float n0 = d0 * r * gA + bA;
        float n1 = d1 * r * gB + bB;
        float acca = brl, accb = 0.f;
        #pragma unroll
        for (int i = 0; i < 32; i++) {
            float v0 = __shfl_sync(0xffffffffu, n0, i);
            float v1 = __shfl_sync(0xffffffffu, n1, i);
            acca += Wr_s[lane * 65 + i] * v0;
            accb += Wr_s[lane * 65 + 32 + i] * v1;
        }
        h = tanhf(acca + accb);
        psum += h;
    }
    float p = psum * (1.f / (float)TSTEPS);
    float o = bo[lane];
    #pragma unroll
    for (int j = 0; j < 32; j++)
        o += Wo_s[lane * 33 + j] * __shfl_sync(0xffffffffu, p, j);
    out[b * 32 + lane] = o;
}

// ---------------- launch ----------------
extern "C" void kernel_launch(void* const* d_in, const int* in_sizes, int n_in,
                              void* d_out, int out_size)
{
    const float* x    = (const float*)d_in[0];
    const float* c1w  = (const float*)d_in[1];
    const float* c1b  = (const float*)d_in[2];
    const float* bn1g = (const float*)d_in[3];
    const float* bn1b = (const float*)d_in[4];
    const float* c2w  = (const float*)d_in[5];
    const float* c2b  = (const float*)d_in[6];
    const float* bn2g = (const float*)d_in[7];
    const float* bn2b = (const float*)d_in[8];
    const float* Wi   = (const float*)d_in[9];
    const float* bi   = (const float*)d_in[10];
    const float* ln1g = (const float*)d_in[11];
    const float* ln1b = (const float*)d_in[12];
    const float* Wh   = (const float*)d_in[13];
    const float* bh   = (const float*)d_in[14];
    const float* ln2g = (const float*)d_in[15];
    const float* ln2b = (const float*)d_in[16];
    const float* Wr   = (const float*)d_in[17];
    const float* br   = (const float*)d_in[18];
    const float* Wo   = (const float*)d_in[19];
    const float* bo   = (const float*)d_in[20];
    float* out = (float*)d_out;

    static bool attr_done = false;
    if (!attr_done) {
        cudaFuncSetAttribute(conv2_kernel, cudaFuncAttributeMaxDynamicSharedMemorySize, SMEM2_BYTES);
        attr_done = true;
    }

    prep_kernel<<<64, 256>>>(c1w, c2w);
    conv1_kernel<<<dim3(8, BATCH), 128>>>(x, c1b);
    bn_finalize_kernel<<<1, 32>>>(0, bn1g, bn1b, 1.f / (float)(BATCH * L1));
    conv2_kernel<<<BATCH, 256, SMEM2_BYTES>>>(c2b);
    bn_finalize_kernel<<<1, 32>>>(1, bn2g, bn2b, 1.f / (float)(BATCH * L2));
    proj_kernel<<<BATCH, 256>>>(Wi, bi, ln1g, ln1b);
    rnn_kernel<<<BATCH / 4, 128>>>(Wh, bh, ln2g, ln2b, Wr, br, Wo, bo, out);
}